// round 15
// baseline (speedup 1.0000x reference)
#include <cuda_runtime.h>
#include <cstdint>

#define NN 4096
#define EE 8192
#define FDIM 64
#define BN_EPS 1e-5f
#define BKT 16
#define NBLK 740
// phase-2 units: lg half-rows [0, 2*EE), pm half-rows [2*EE, 2*EE + 2*NN)
#define POPUNITS (2 * EE + 2 * NN)

// ---------------- device scratch ----------------
__device__ float g_x[NN * FDIM];        // raw x (pre-BN)
__device__ float g_lg_y[EE * FDIM];     // accumulated via RED
__device__ float g_stats[256];          // [0:128) x stats, [128:256) y stats
__device__ unsigned g_row_ctr;
__device__ int   g_bkt_cnt[EE];
__device__ int   g_bkt_n[EE * BKT];
__device__ float g_bkt_v[EE * BKT];

// ---------------- init: zero lg_y + buckets + stats + counter ----------------
__global__ __launch_bounds__(256) void k_init() {
    int idx = blockIdx.x * 256 + threadIdx.x;    // 512*256 = 131072
    reinterpret_cast<float4*>(g_lg_y)[idx] = make_float4(0.f, 0.f, 0.f, 0.f);
    if (idx < EE) g_bkt_cnt[idx] = 0;
    if (idx < 256) g_stats[idx] = 0.f;
    if (idx == 0) g_row_ctr = 0u;
}

// ---------------- helpers ----------------
__device__ __forceinline__ unsigned nz4(float4 v) {
    return __float_as_uint(v.x) | __float_as_uint(v.y) |
           __float_as_uint(v.z) | __float_as_uint(v.w);
}

__device__ __forceinline__ void gath_chunk(float4 v, unsigned ored, int colbase, int lane,
                                           const float* __restrict__ B,
                                           float& acc0, float& acc1) {
    unsigned mask = __ballot_sync(0xffffffffu, ored != 0u);
    while (mask) {
        int src = __ffs(mask) - 1;
        mask &= mask - 1;
        float b0 = __shfl_sync(0xffffffffu, v.x, src);
        float b1 = __shfl_sync(0xffffffffu, v.y, src);
        float b2 = __shfl_sync(0xffffffffu, v.z, src);
        float b3 = __shfl_sync(0xffffffffu, v.w, src);
        const float* bp = B + (size_t)(colbase + (src << 2)) * FDIM + lane;
        if (b0 != 0.f) { acc0 = fmaf(b0, bp[0],   acc0); acc1 = fmaf(b0, bp[32],  acc1); }
        if (b1 != 0.f) { acc0 = fmaf(b1, bp[64],  acc0); acc1 = fmaf(b1, bp[96],  acc1); }
        if (b2 != 0.f) { acc0 = fmaf(b2, bp[128], acc0); acc1 = fmaf(b2, bp[160], acc1); }
        if (b3 != 0.f) { acc0 = fmaf(b3, bp[192], acc0); acc1 = fmaf(b3, bp[224], acc1); }
    }
}

__device__ __forceinline__ void pm_emit(float4 v, int col0, int n) {
    float vals[4] = {v.x, v.y, v.z, v.w};
    #pragma unroll
    for (int j = 0; j < 4; ++j) {
        if (vals[j] != 0.f) {
            int e = col0 + j;
            int slot = atomicAdd(&g_bkt_cnt[e], 1);
            if (slot < BKT) {
                g_bkt_n[e * BKT + slot] = n;
                g_bkt_v[e * BKT + slot] = vals[j];
            }
        }
    }
}

// scan a 4096-float range (8 groups of 512), gather-accumulate
__device__ __forceinline__ void scan_gather_half(const float4* __restrict__ arow,
                                                 int colstart,  // 0 or 4096
                                                 const float* __restrict__ y,
                                                 int lane, float& acc0, float& acc1) {
    acc0 = 0.f; acc1 = 0.f;
    int f0 = colstart >> 2;
    #pragma unroll 1
    for (int g = 0; g < 8; ++g) {
        int fb = f0 + (g << 7) + lane;
        float4 v0 = __ldcs(arow + fb);
        float4 v1 = __ldcs(arow + fb + 32);
        float4 v2 = __ldcs(arow + fb + 64);
        float4 v3 = __ldcs(arow + fb + 96);
        unsigned o0 = nz4(v0), o1 = nz4(v1), o2 = nz4(v2), o3 = nz4(v3);
        if (__ballot_sync(0xffffffffu, (o0 | o1 | o2 | o3) != 0u)) {
            int cb = colstart + (g << 9);
            gath_chunk(v0, o0, cb,       lane, y, acc0, acc1);
            gath_chunk(v1, o1, cb + 128, lane, y, acc0, acc1);
            gath_chunk(v2, o2, cb + 256, lane, y, acc0, acc1);
            gath_chunk(v3, o3, cb + 384, lane, y, acc0, acc1);
        }
    }
}

// ---------------- fused mega-scan: static pd+x phase, then dynamic half-row pop ----------------
__global__ void __launch_bounds__(256, 5) k_megascan(const float* __restrict__ pd,
                                                     const float* __restrict__ lg,
                                                     const float* __restrict__ pm,
                                                     const float* __restrict__ y,
                                                     const float* __restrict__ tw,
                                                     const float* __restrict__ tb,
                                                     const float* __restrict__ trw,
                                                     const float* __restrict__ trb) {
    __shared__ float s_in[16 * 64];
    __shared__ float red[256], red2[256];
    int t = threadIdx.x;
    int lane = t & 31;
    int w = t >> 5;

    // ---- phase 1 (blocks 0..255): scan 16 owned pd rows + x-linear in place ----
    if (blockIdx.x < 256) {
        int rowbase = blockIdx.x * 16;
        #pragma unroll 1
        for (int r = 0; r < 2; ++r) {
            int rl = 2 * w + r;
            const float4* arow = reinterpret_cast<const float4*>(pd + (size_t)(rowbase + rl) * EE);
            float a0h, a1h, a0l, a1l;
            scan_gather_half(arow, 0,    y, lane, a0h, a1h);
            scan_gather_half(arow, 4096, y, lane, a0l, a1l);
            s_in[rl * 64 + lane]      = a0h + a0l;
            s_in[rl * 64 + lane + 32] = a1h + a1l;
        }
        __syncthreads();

        int c = t & 63, slot = t >> 6;
        const float* wt; float bias; bool dorelu;
        if (c < 32) { wt = tw + c * 64;         bias = tb[c];        dorelu = false; }
        else        { wt = trw + (c - 32) * 64; bias = trb[c - 32];  dorelu = true;  }
        float acc[4] = {bias, bias, bias, bias};
        #pragma unroll
        for (int f = 0; f < 64; f += 4) {
            float4 wv = *reinterpret_cast<const float4*>(wt + f);
            #pragma unroll
            for (int j = 0; j < 4; ++j) {
                float4 pv = *reinterpret_cast<const float4*>(&s_in[(slot + 4 * j) * 64 + f]);
                acc[j] = fmaf(wv.x, pv.x, fmaf(wv.y, pv.y, fmaf(wv.z, pv.z, fmaf(wv.w, pv.w, acc[j]))));
            }
        }
        float s = 0.f, sq = 0.f;
        #pragma unroll
        for (int j = 0; j < 4; ++j) {
            float v = acc[j];
            if (dorelu) v = fmaxf(v, 0.f);
            g_x[(size_t)(rowbase + slot + 4 * j) * 64 + c] = v;
            s += v; sq += v * v;
        }
        red[t] = s; red2[t] = sq;
        __syncthreads();
        if (slot == 0) {
            atomicAdd(&g_stats[c],      red[c] + red[64 + c] + red[128 + c] + red[192 + c]);
            atomicAdd(&g_stats[64 + c], red2[c] + red2[64 + c] + red2[128 + c] + red2[192 + c]);
        }
    }

    // ---- phase 2 (all blocks): dynamic pop over half-row units ----
    while (true) {
        unsigned uid;
        if (lane == 0) uid = atomicAdd(&g_row_ctr, 1u);
        uid = __shfl_sync(0xffffffffu, uid, 0);
        if (uid >= POPUNITS) return;

        if (uid < 2u * EE) {
            int row = (int)(uid >> 1);
            int colstart = (uid & 1u) ? 4096 : 0;
            const float4* arow = reinterpret_cast<const float4*>(lg + (size_t)row * EE);
            float acc0, acc1;
            scan_gather_half(arow, colstart, y, lane, acc0, acc1);
            // combine the two halves via RED (g_lg_y zeroed in k_init)
            if (acc0 != 0.f) atomicAdd(&g_lg_y[(size_t)row * FDIM + lane],      acc0);
            if (acc1 != 0.f) atomicAdd(&g_lg_y[(size_t)row * FDIM + lane + 32], acc1);
        } else {
            unsigned pu = uid - 2u * EE;
            int row = (int)(pu >> 1);
            int colstart = (pu & 1u) ? 4096 : 0;
            const float4* arow = reinterpret_cast<const float4*>(pm + (size_t)row * EE);
            int f0 = colstart >> 2;
            #pragma unroll 1
            for (int g = 0; g < 8; ++g) {
                int fb = f0 + (g << 7) + lane;
                float4 v0 = __ldcs(arow + fb);
                float4 v1 = __ldcs(arow + fb + 32);
                float4 v2 = __ldcs(arow + fb + 64);
                float4 v3 = __ldcs(arow + fb + 96);
                unsigned o0 = nz4(v0), o1 = nz4(v1), o2 = nz4(v2), o3 = nz4(v3);
                if (__ballot_sync(0xffffffffu, (o0 | o1 | o2 | o3) != 0u)) {
                    int cb = colstart + (g << 9) + (lane << 2);
                    if (o0) pm_emit(v0, cb,       row);
                    if (o1) pm_emit(v1, cb + 128, row);
                    if (o2) pm_emit(v2, cb + 256, row);
                    if (o3) pm_emit(v3, cb + 384, row);
                }
            }
        }
    }
}

// ---------------- y: inline pm gather (BN-x fused) + combine + relu + BN-y stats -> out ----------------
__global__ __launch_bounds__(256) void k_y_linear(const float* __restrict__ gaw,
                                                  const float* __restrict__ gab,
                                                  const float* __restrict__ gxw,
                                                  const float* __restrict__ gxb,
                                                  const float* __restrict__ garw,
                                                  const float* __restrict__ garb,
                                                  const float* __restrict__ gxrw,
                                                  const float* __restrict__ gxrb,
                                                  const float* __restrict__ bxw,
                                                  const float* __restrict__ bxb,
                                                  float* __restrict__ out) {
    __shared__ float s_lg[16 * 64];
    __shared__ float s_pm[16 * 64];
    __shared__ float s_sc[64], s_sh[64];
    __shared__ float red[256], red2[256];
    int t = threadIdx.x;
    int lane = t & 31;
    int w = t >> 5;
    int rowbase = blockIdx.x * 16;

    if (t < 64) {
        const float invn = 1.f / NN;
        float m = g_stats[t] * invn;
        float var = g_stats[64 + t] * invn - m * m;
        float sc = bxw[t] * rsqrtf(var + BN_EPS);
        s_sc[t] = sc;
        s_sh[t] = bxb[t] - m * sc;
    }
    reinterpret_cast<float4*>(s_lg)[t] =
        reinterpret_cast<const float4*>(g_lg_y + (size_t)rowbase * 64)[t];
    __syncthreads();

    // pm gather: warp w handles edges rowbase+2w, rowbase+2w+1
    {
        float scl0 = s_sc[lane],      shl0 = s_sh[lane];
        float scl1 = s_sc[lane + 32], shl1 = s_sh[lane + 32];
        #pragma unroll
        for (int h = 0; h < 2; ++h) {
            int eslot = 2 * w + h;
            int e = rowbase + eslot;
            int cnt = g_bkt_cnt[e];
            if (cnt > BKT) cnt = BKT;
            float a0 = 0.f, a1 = 0.f;
            for (int j = 0; j < cnt; ++j) {
                int n = g_bkt_n[e * BKT + j];
                float val = g_bkt_v[e * BKT + j];
                float xv0 = g_x[(size_t)n * 64 + lane];
                float xv1 = g_x[(size_t)n * 64 + lane + 32];
                a0 = fmaf(val, fmaf(xv0, scl0, shl0), a0);
                a1 = fmaf(val, fmaf(xv1, scl1, shl1), a1);
            }
            s_pm[eslot * 64 + lane]      = a0;
            s_pm[eslot * 64 + lane + 32] = a1;
        }
    }
    __syncthreads();

    int c = t & 63, slot = t >> 6;
    const float *wa, *wx; float bias; bool dorelu;
    if (c < 32) { wa = gaw + c * 64;   wx = gxw + c * 64;
                  bias = gab[c] + gxb[c];            dorelu = false; }
    else        { int cr = c - 32;
                  wa = garw + cr * 64; wx = gxrw + cr * 64;
                  bias = garb[cr] + gxrb[cr];        dorelu = true;  }
    float acc[4] = {bias, bias, bias, bias};
    #pragma unroll
    for (int f = 0; f < 64; f += 4) {
        float4 wav = *reinterpret_cast<const float4*>(wa + f);
        float4 wxv = *reinterpret_cast<const float4*>(wx + f);
        #pragma unroll
        for (int j = 0; j < 4; ++j) {
            float4 pa = *reinterpret_cast<const float4*>(&s_lg[(slot + 4 * j) * 64 + f]);
            float4 px = *reinterpret_cast<const float4*>(&s_pm[(slot + 4 * j) * 64 + f]);
            float a = acc[j];
            a = fmaf(wav.x, pa.x, fmaf(wav.y, pa.y, fmaf(wav.z, pa.z, fmaf(wav.w, pa.w, a))));
            a = fmaf(wxv.x, px.x, fmaf(wxv.y, px.y, fmaf(wxv.z, px.z, fmaf(wxv.w, px.w, a))));
            acc[j] = a;
        }
    }
    float s = 0.f, sq = 0.f;
    #pragma unroll
    for (int j = 0; j < 4; ++j) {
        float v = acc[j];
        if (dorelu) v = fmaxf(v, 0.f);
        out[(size_t)(rowbase + slot + 4 * j) * 64 + c] = v;
        s += v; sq += v * v;
    }
    red[t] = s; red2[t] = sq;
    __syncthreads();
    if (slot == 0) {
        atomicAdd(&g_stats[128 + c], red[c] + red[64 + c] + red[128 + c] + red[192 + c]);
        atomicAdd(&g_stats[192 + c], red2[c] + red2[64 + c] + red2[128 + c] + red2[192 + c]);
    }
}

// ---------------- final BN on y (vectorized, in place) ----------------
__global__ __launch_bounds__(256) void k_bn_y(float4* __restrict__ buf,
                                              const float* __restrict__ w,
                                              const float* __restrict__ b) {
    int idx = blockIdx.x * 256 + threadIdx.x;
    const float inve = 1.f / EE;
    int c0 = (idx & 15) << 2;
    float4 v = buf[idx];
    float* vp = reinterpret_cast<float*>(&v);
    #pragma unroll
    for (int j = 0; j < 4; ++j) {
        int c = c0 + j;
        float m = g_stats[128 + c] * inve;
        float var = g_stats[192 + c] * inve - m * m;
        float sc = w[c] * rsqrtf(var + BN_EPS);
        vp[j] = (vp[j] - m) * sc + b[c];
    }
    buf[idx] = v;
}

// ---------------- launch ----------------
extern "C" void kernel_launch(void* const* d_in, const int* in_sizes, int n_in,
                              void* d_out, int out_size) {
    const float* y    = (const float*)d_in[0];
    const float* lg   = (const float*)d_in[3];
    const float* pm   = (const float*)d_in[4];
    const float* pd   = (const float*)d_in[5];
    const float* tw   = (const float*)d_in[6];
    const float* tb   = (const float*)d_in[7];
    const float* trw  = (const float*)d_in[8];
    const float* trb  = (const float*)d_in[9];
    const float* gaw  = (const float*)d_in[10];
    const float* gab  = (const float*)d_in[11];
    const float* gxw  = (const float*)d_in[12];
    const float* gxb  = (const float*)d_in[13];
    const float* garw = (const float*)d_in[14];
    const float* garb = (const float*)d_in[15];
    const float* gxrw = (const float*)d_in[16];
    const float* gxrb = (const float*)d_in[17];
    const float* bxw  = (const float*)d_in[18];
    const float* bxb  = (const float*)d_in[19];
    const float* byw  = (const float*)d_in[20];
    const float* byb  = (const float*)d_in[21];
    float* out = (float*)d_out;

    k_init<<<512, 256>>>();
    k_megascan<<<NBLK, 256>>>(pd, lg, pm, y, tw, tb, trw, trb);
    k_y_linear<<<EE / 16, 256>>>(gaw, gab, gxw, gxb, garw, garb, gxrw, gxrb,
                                 bxw, bxb, out);
    k_bn_y<<<512, 256>>>((float4*)out, byw, byb);
}

// round 16
// speedup vs baseline: 1.0310x; 1.0310x over previous
#include <cuda_runtime.h>
#include <cstdint>

#define NN 4096
#define EE 8192
#define FDIM 64
#define BN_EPS 1e-5f
#define BKT 16
#define NBLK 740
// phase-2 units: lg whole rows [0, EE), then pm quarter-rows [EE, EE + 4*NN)
#define POPUNITS (EE + 4 * NN)

// ---------------- device scratch ----------------
__device__ float g_x[NN * FDIM];        // raw x (pre-BN)
__device__ float g_lg_y[EE * FDIM];
__device__ float g_stats[256];          // [0:128) x stats, [128:256) y stats
__device__ unsigned g_row_ctr;
__device__ int   g_bkt_cnt[EE];
__device__ int   g_bkt_n[EE * BKT];
__device__ float g_bkt_v[EE * BKT];

// ---------------- init ----------------
__global__ __launch_bounds__(256) void k_init() {
    int idx = blockIdx.x * 256 + threadIdx.x;    // 32*256 = 8192
    g_bkt_cnt[idx] = 0;
    if (idx < 256) g_stats[idx] = 0.f;
    if (idx == 0) g_row_ctr = 0u;
}

// ---------------- helpers ----------------
__device__ __forceinline__ unsigned nz4(float4 v) {
    return __float_as_uint(v.x) | __float_as_uint(v.y) |
           __float_as_uint(v.z) | __float_as_uint(v.w);
}

__device__ __forceinline__ void gath_chunk(float4 v, unsigned ored, int colbase, int lane,
                                           const float* __restrict__ B,
                                           float& acc0, float& acc1) {
    unsigned mask = __ballot_sync(0xffffffffu, ored != 0u);
    while (mask) {
        int src = __ffs(mask) - 1;
        mask &= mask - 1;
        float b0 = __shfl_sync(0xffffffffu, v.x, src);
        float b1 = __shfl_sync(0xffffffffu, v.y, src);
        float b2 = __shfl_sync(0xffffffffu, v.z, src);
        float b3 = __shfl_sync(0xffffffffu, v.w, src);
        const float* bp = B + (size_t)(colbase + (src << 2)) * FDIM + lane;
        if (b0 != 0.f) { acc0 = fmaf(b0, bp[0],   acc0); acc1 = fmaf(b0, bp[32],  acc1); }
        if (b1 != 0.f) { acc0 = fmaf(b1, bp[64],  acc0); acc1 = fmaf(b1, bp[96],  acc1); }
        if (b2 != 0.f) { acc0 = fmaf(b2, bp[128], acc0); acc1 = fmaf(b2, bp[160], acc1); }
        if (b3 != 0.f) { acc0 = fmaf(b3, bp[192], acc0); acc1 = fmaf(b3, bp[224], acc1); }
    }
}

__device__ __forceinline__ void pm_emit(float4 v, int col0, int n) {
    float vals[4] = {v.x, v.y, v.z, v.w};
    #pragma unroll
    for (int j = 0; j < 4; ++j) {
        if (vals[j] != 0.f) {
            int e = col0 + j;
            int slot = atomicAdd(&g_bkt_cnt[e], 1);
            if (slot < BKT) {
                g_bkt_n[e * BKT + slot] = n;
                g_bkt_v[e * BKT + slot] = vals[j];
            }
        }
    }
}

// scan one full gather row (pd/lg): 16 groups of 512 floats
__device__ __forceinline__ void scan_gather_row(const float4* __restrict__ arow,
                                                const float* __restrict__ y,
                                                int lane, float& acc0, float& acc1) {
    acc0 = 0.f; acc1 = 0.f;
    #pragma unroll 1
    for (int g = 0; g < EE / 512; ++g) {
        int fb = (g << 7) + lane;
        float4 v0 = __ldcs(arow + fb);
        float4 v1 = __ldcs(arow + fb + 32);
        float4 v2 = __ldcs(arow + fb + 64);
        float4 v3 = __ldcs(arow + fb + 96);
        unsigned o0 = nz4(v0), o1 = nz4(v1), o2 = nz4(v2), o3 = nz4(v3);
        if (__ballot_sync(0xffffffffu, (o0 | o1 | o2 | o3) != 0u)) {
            int cb = g << 9;
            gath_chunk(v0, o0, cb,       lane, y, acc0, acc1);
            gath_chunk(v1, o1, cb + 128, lane, y, acc0, acc1);
            gath_chunk(v2, o2, cb + 256, lane, y, acc0, acc1);
            gath_chunk(v3, o3, cb + 384, lane, y, acc0, acc1);
        }
    }
}

// ---------------- fused mega-scan: static pd+x phase, then dynamic pop ----------------
// phase 2: lg whole rows first, then pm quarter-rows (free split; emit is range-agnostic)
__global__ void __launch_bounds__(256, 5) k_megascan(const float* __restrict__ pd,
                                                     const float* __restrict__ lg,
                                                     const float* __restrict__ pm,
                                                     const float* __restrict__ y,
                                                     const float* __restrict__ tw,
                                                     const float* __restrict__ tb,
                                                     const float* __restrict__ trw,
                                                     const float* __restrict__ trb) {
    __shared__ float s_in[16 * 64];
    __shared__ float red[256], red2[256];
    int t = threadIdx.x;
    int lane = t & 31;
    int w = t >> 5;

    // ---- phase 1 (blocks 0..255): scan 16 owned pd rows + x-linear in place ----
    if (blockIdx.x < 256) {
        int rowbase = blockIdx.x * 16;
        #pragma unroll 1
        for (int r = 0; r < 2; ++r) {
            int rl = 2 * w + r;
            const float4* arow = reinterpret_cast<const float4*>(pd + (size_t)(rowbase + rl) * EE);
            float acc0, acc1;
            scan_gather_row(arow, y, lane, acc0, acc1);
            s_in[rl * 64 + lane]      = acc0;
            s_in[rl * 64 + lane + 32] = acc1;
        }
        __syncthreads();

        int c = t & 63, slot = t >> 6;
        const float* wt; float bias; bool dorelu;
        if (c < 32) { wt = tw + c * 64;         bias = tb[c];        dorelu = false; }
        else        { wt = trw + (c - 32) * 64; bias = trb[c - 32];  dorelu = true;  }
        float acc[4] = {bias, bias, bias, bias};
        #pragma unroll
        for (int f = 0; f < 64; f += 4) {
            float4 wv = *reinterpret_cast<const float4*>(wt + f);
            #pragma unroll
            for (int j = 0; j < 4; ++j) {
                float4 pv = *reinterpret_cast<const float4*>(&s_in[(slot + 4 * j) * 64 + f]);
                acc[j] = fmaf(wv.x, pv.x, fmaf(wv.y, pv.y, fmaf(wv.z, pv.z, fmaf(wv.w, pv.w, acc[j]))));
            }
        }
        float s = 0.f, sq = 0.f;
        #pragma unroll
        for (int j = 0; j < 4; ++j) {
            float v = acc[j];
            if (dorelu) v = fmaxf(v, 0.f);
            g_x[(size_t)(rowbase + slot + 4 * j) * 64 + c] = v;
            s += v; sq += v * v;
        }
        red[t] = s; red2[t] = sq;
        __syncthreads();
        if (slot == 0) {
            atomicAdd(&g_stats[c],      red[c] + red[64 + c] + red[128 + c] + red[192 + c]);
            atomicAdd(&g_stats[64 + c], red2[c] + red2[64 + c] + red2[128 + c] + red2[192 + c]);
        }
    }

    // ---- phase 2 (all blocks): dynamic pop ----
    while (true) {
        unsigned uid;
        if (lane == 0) uid = atomicAdd(&g_row_ctr, 1u);
        uid = __shfl_sync(0xffffffffu, uid, 0);
        if (uid >= POPUNITS) return;

        if (uid < (unsigned)EE) {
            int row = (int)uid;
            const float4* arow = reinterpret_cast<const float4*>(lg + (size_t)row * EE);
            float acc0, acc1;
            scan_gather_row(arow, y, lane, acc0, acc1);
            g_lg_y[(size_t)row * FDIM + lane]      = acc0;
            g_lg_y[(size_t)row * FDIM + lane + 32] = acc1;
        } else {
            unsigned pu = uid - EE;
            int row = (int)(pu >> 2);
            int colstart = (int)(pu & 3u) << 11;        // quarter: 2048 floats
            const float4* arow = reinterpret_cast<const float4*>(pm + (size_t)row * EE);
            int f0 = colstart >> 2;
            #pragma unroll 1
            for (int g = 0; g < 4; ++g) {
                int fb = f0 + (g << 7) + lane;
                float4 v0 = __ldcs(arow + fb);
                float4 v1 = __ldcs(arow + fb + 32);
                float4 v2 = __ldcs(arow + fb + 64);
                float4 v3 = __ldcs(arow + fb + 96);
                unsigned o0 = nz4(v0), o1 = nz4(v1), o2 = nz4(v2), o3 = nz4(v3);
                if (__ballot_sync(0xffffffffu, (o0 | o1 | o2 | o3) != 0u)) {
                    int cb = colstart + (g << 9) + (lane << 2);
                    if (o0) pm_emit(v0, cb,       row);
                    if (o1) pm_emit(v1, cb + 128, row);
                    if (o2) pm_emit(v2, cb + 256, row);
                    if (o3) pm_emit(v3, cb + 384, row);
                }
            }
        }
    }
}

// ---------------- y: inline pm gather (BN-x fused) + combine + relu + BN-y stats -> out ----------------
__global__ __launch_bounds__(256) void k_y_linear(const float* __restrict__ gaw,
                                                  const float* __restrict__ gab,
                                                  const float* __restrict__ gxw,
                                                  const float* __restrict__ gxb,
                                                  const float* __restrict__ garw,
                                                  const float* __restrict__ garb,
                                                  const float* __restrict__ gxrw,
                                                  const float* __restrict__ gxrb,
                                                  const float* __restrict__ bxw,
                                                  const float* __restrict__ bxb,
                                                  float* __restrict__ out) {
    __shared__ float s_lg[16 * 64];
    __shared__ float s_pm[16 * 64];
    __shared__ float s_sc[64], s_sh[64];
    __shared__ float red[256], red2[256];
    int t = threadIdx.x;
    int lane = t & 31;
    int w = t >> 5;
    int rowbase = blockIdx.x * 16;

    if (t < 64) {
        const float invn = 1.f / NN;
        float m = g_stats[t] * invn;
        float var = g_stats[64 + t] * invn - m * m;
        float sc = bxw[t] * rsqrtf(var + BN_EPS);
        s_sc[t] = sc;
        s_sh[t] = bxb[t] - m * sc;
    }
    reinterpret_cast<float4*>(s_lg)[t] =
        reinterpret_cast<const float4*>(g_lg_y + (size_t)rowbase * 64)[t];
    __syncthreads();

    // pm gather: warp w handles edges rowbase+2w, rowbase+2w+1
    {
        float scl0 = s_sc[lane],      shl0 = s_sh[lane];
        float scl1 = s_sc[lane + 32], shl1 = s_sh[lane + 32];
        #pragma unroll
        for (int h = 0; h < 2; ++h) {
            int eslot = 2 * w + h;
            int e = rowbase + eslot;
            int cnt = g_bkt_cnt[e];
            if (cnt > BKT) cnt = BKT;
            float a0 = 0.f, a1 = 0.f;
            for (int j = 0; j < cnt; ++j) {
                int n = g_bkt_n[e * BKT + j];
                float val = g_bkt_v[e * BKT + j];
                float xv0 = g_x[(size_t)n * 64 + lane];
                float xv1 = g_x[(size_t)n * 64 + lane + 32];
                a0 = fmaf(val, fmaf(xv0, scl0, shl0), a0);
                a1 = fmaf(val, fmaf(xv1, scl1, shl1), a1);
            }
            s_pm[eslot * 64 + lane]      = a0;
            s_pm[eslot * 64 + lane + 32] = a1;
        }
    }
    __syncthreads();

    int c = t & 63, slot = t >> 6;
    const float *wa, *wx; float bias; bool dorelu;
    if (c < 32) { wa = gaw + c * 64;   wx = gxw + c * 64;
                  bias = gab[c] + gxb[c];            dorelu = false; }
    else        { int cr = c - 32;
                  wa = garw + cr * 64; wx = gxrw + cr * 64;
                  bias = garb[cr] + gxrb[cr];        dorelu = true;  }
    float acc[4] = {bias, bias, bias, bias};
    #pragma unroll
    for (int f = 0; f < 64; f += 4) {
        float4 wav = *reinterpret_cast<const float4*>(wa + f);
        float4 wxv = *reinterpret_cast<const float4*>(wx + f);
        #pragma unroll
        for (int j = 0; j < 4; ++j) {
            float4 pa = *reinterpret_cast<const float4*>(&s_lg[(slot + 4 * j) * 64 + f]);
            float4 px = *reinterpret_cast<const float4*>(&s_pm[(slot + 4 * j) * 64 + f]);
            float a = acc[j];
            a = fmaf(wav.x, pa.x, fmaf(wav.y, pa.y, fmaf(wav.z, pa.z, fmaf(wav.w, pa.w, a))));
            a = fmaf(wxv.x, px.x, fmaf(wxv.y, px.y, fmaf(wxv.z, px.z, fmaf(wxv.w, px.w, a))));
            acc[j] = a;
        }
    }
    float s = 0.f, sq = 0.f;
    #pragma unroll
    for (int j = 0; j < 4; ++j) {
        float v = acc[j];
        if (dorelu) v = fmaxf(v, 0.f);
        out[(size_t)(rowbase + slot + 4 * j) * 64 + c] = v;
        s += v; sq += v * v;
    }
    red[t] = s; red2[t] = sq;
    __syncthreads();
    if (slot == 0) {
        atomicAdd(&g_stats[128 + c], red[c] + red[64 + c] + red[128 + c] + red[192 + c]);
        atomicAdd(&g_stats[192 + c], red2[c] + red2[64 + c] + red2[128 + c] + red2[192 + c]);
    }
}

// ---------------- final BN on y (vectorized, in place) ----------------
__global__ __launch_bounds__(256) void k_bn_y(float4* __restrict__ buf,
                                              const float* __restrict__ w,
                                              const float* __restrict__ b) {
    int idx = blockIdx.x * 256 + threadIdx.x;
    const float inve = 1.f / EE;
    int c0 = (idx & 15) << 2;
    float4 v = buf[idx];
    float* vp = reinterpret_cast<float*>(&v);
    #pragma unroll
    for (int j = 0; j < 4; ++j) {
        int c = c0 + j;
        float m = g_stats[128 + c] * inve;
        float var = g_stats[192 + c] * inve - m * m;
        float sc = w[c] * rsqrtf(var + BN_EPS);
        vp[j] = (vp[j] - m) * sc + b[c];
    }
    buf[idx] = v;
}

// ---------------- launch ----------------
extern "C" void kernel_launch(void* const* d_in, const int* in_sizes, int n_in,
                              void* d_out, int out_size) {
    const float* y    = (const float*)d_in[0];
    const float* lg   = (const float*)d_in[3];
    const float* pm   = (const float*)d_in[4];
    const float* pd   = (const float*)d_in[5];
    const float* tw   = (const float*)d_in[6];
    const float* tb   = (const float*)d_in[7];
    const float* trw  = (const float*)d_in[8];
    const float* trb  = (const float*)d_in[9];
    const float* gaw  = (const float*)d_in[10];
    const float* gab  = (const float*)d_in[11];
    const float* gxw  = (const float*)d_in[12];
    const float* gxb  = (const float*)d_in[13];
    const float* garw = (const float*)d_in[14];
    const float* garb = (const float*)d_in[15];
    const float* gxrw = (const float*)d_in[16];
    const float* gxrb = (const float*)d_in[17];
    const float* bxw  = (const float*)d_in[18];
    const float* bxb  = (const float*)d_in[19];
    const float* byw  = (const float*)d_in[20];
    const float* byb  = (const float*)d_in[21];
    float* out = (float*)d_out;

    k_init<<<32, 256>>>();
    k_megascan<<<NBLK, 256>>>(pd, lg, pm, y, tw, tb, trw, trb);
    k_y_linear<<<EE / 16, 256>>>(gaw, gab, gxw, gxb, garw, garb, gxrw, gxrb,
                                 bxw, bxb, out);
    k_bn_y<<<512, 256>>>((float4*)out, byw, byb);
}

// round 17
// speedup vs baseline: 1.0829x; 1.0504x over previous
#include <cuda_runtime.h>
#include <cstdint>

#define NN 4096
#define EE 8192
#define FDIM 64
#define BN_EPS 1e-5f
#define BKT 16
#define NBLK 740
#define POPROWS (EE + NN)   // lg rows then pm rows

// ---------------- device scratch (zero at module load; recycled across replays) ----------------
__device__ float g_x[NN * FDIM];        // raw x (pre-BN)
__device__ float g_lg_y[EE * FDIM];
__device__ float g_stats[256];          // [0:128) x stats, [128:256) y stats
__device__ unsigned g_row_ctr;
__device__ int   g_bkt_cnt[EE];
__device__ int   g_bkt_n[EE * BKT];
__device__ float g_bkt_v[EE * BKT];

// ---------------- helpers ----------------
__device__ __forceinline__ unsigned nz4(float4 v) {
    return __float_as_uint(v.x) | __float_as_uint(v.y) |
           __float_as_uint(v.z) | __float_as_uint(v.w);
}

__device__ __forceinline__ void gath_chunk(float4 v, unsigned ored, int colbase, int lane,
                                           const float* __restrict__ B,
                                           float& acc0, float& acc1) {
    unsigned mask = __ballot_sync(0xffffffffu, ored != 0u);
    while (mask) {
        int src = __ffs(mask) - 1;
        mask &= mask - 1;
        float b0 = __shfl_sync(0xffffffffu, v.x, src);
        float b1 = __shfl_sync(0xffffffffu, v.y, src);
        float b2 = __shfl_sync(0xffffffffu, v.z, src);
        float b3 = __shfl_sync(0xffffffffu, v.w, src);
        const float* bp = B + (size_t)(colbase + (src << 2)) * FDIM + lane;
        if (b0 != 0.f) { acc0 = fmaf(b0, bp[0],   acc0); acc1 = fmaf(b0, bp[32],  acc1); }
        if (b1 != 0.f) { acc0 = fmaf(b1, bp[64],  acc0); acc1 = fmaf(b1, bp[96],  acc1); }
        if (b2 != 0.f) { acc0 = fmaf(b2, bp[128], acc0); acc1 = fmaf(b2, bp[160], acc1); }
        if (b3 != 0.f) { acc0 = fmaf(b3, bp[192], acc0); acc1 = fmaf(b3, bp[224], acc1); }
    }
}

__device__ __forceinline__ void pm_emit(float4 v, int col0, int n) {
    float vals[4] = {v.x, v.y, v.z, v.w};
    #pragma unroll
    for (int j = 0; j < 4; ++j) {
        if (vals[j] != 0.f) {
            int e = col0 + j;
            int slot = atomicAdd(&g_bkt_cnt[e], 1);
            if (slot < BKT) {
                g_bkt_n[e * BKT + slot] = n;
                g_bkt_v[e * BKT + slot] = vals[j];
            }
        }
    }
}

// scan one full gather row (pd/lg): 16 groups of 512 floats
__device__ __forceinline__ void scan_gather_row(const float4* __restrict__ arow,
                                                const float* __restrict__ y,
                                                int lane, float& acc0, float& acc1) {
    acc0 = 0.f; acc1 = 0.f;
    #pragma unroll 1
    for (int g = 0; g < EE / 512; ++g) {
        int fb = (g << 7) + lane;
        float4 v0 = __ldcs(arow + fb);
        float4 v1 = __ldcs(arow + fb + 32);
        float4 v2 = __ldcs(arow + fb + 64);
        float4 v3 = __ldcs(arow + fb + 96);
        unsigned o0 = nz4(v0), o1 = nz4(v1), o2 = nz4(v2), o3 = nz4(v3);
        if (__ballot_sync(0xffffffffu, (o0 | o1 | o2 | o3) != 0u)) {
            int cb = g << 9;
            gath_chunk(v0, o0, cb,       lane, y, acc0, acc1);
            gath_chunk(v1, o1, cb + 128, lane, y, acc0, acc1);
            gath_chunk(v2, o2, cb + 256, lane, y, acc0, acc1);
            gath_chunk(v3, o3, cb + 384, lane, y, acc0, acc1);
        }
    }
}

// ---------------- fused mega-scan: static pd+x phase, then dynamic lg/pm pop ----------------
// block 0 additionally zeroes the y-stats (consumed by bn_y, produced by y_linear;
// nothing in this kernel touches them, so the kernel boundary is the only ordering needed).
__global__ void __launch_bounds__(256, 5) k_megascan(const float* __restrict__ pd,
                                                     const float* __restrict__ lg,
                                                     const float* __restrict__ pm,
                                                     const float* __restrict__ y,
                                                     const float* __restrict__ tw,
                                                     const float* __restrict__ tb,
                                                     const float* __restrict__ trw,
                                                     const float* __restrict__ trb) {
    __shared__ float s_in[16 * 64];
    __shared__ float red[256], red2[256];
    int t = threadIdx.x;
    int lane = t & 31;
    int w = t >> 5;

    if (blockIdx.x == 0 && t < 128) g_stats[128 + t] = 0.f;

    // ---- phase 1 (blocks 0..255): scan 16 owned pd rows + x-linear in place ----
    if (blockIdx.x < 256) {
        int rowbase = blockIdx.x * 16;
        #pragma unroll 1
        for (int r = 0; r < 2; ++r) {
            int rl = 2 * w + r;
            const float4* arow = reinterpret_cast<const float4*>(pd + (size_t)(rowbase + rl) * EE);
            float acc0, acc1;
            scan_gather_row(arow, y, lane, acc0, acc1);
            s_in[rl * 64 + lane]      = acc0;
            s_in[rl * 64 + lane + 32] = acc1;
        }
        __syncthreads();

        int c = t & 63, slot = t >> 6;
        const float* wt; float bias; bool dorelu;
        if (c < 32) { wt = tw + c * 64;         bias = tb[c];        dorelu = false; }
        else        { wt = trw + (c - 32) * 64; bias = trb[c - 32];  dorelu = true;  }
        float acc[4] = {bias, bias, bias, bias};
        #pragma unroll
        for (int f = 0; f < 64; f += 4) {
            float4 wv = *reinterpret_cast<const float4*>(wt + f);
            #pragma unroll
            for (int j = 0; j < 4; ++j) {
                float4 pv = *reinterpret_cast<const float4*>(&s_in[(slot + 4 * j) * 64 + f]);
                acc[j] = fmaf(wv.x, pv.x, fmaf(wv.y, pv.y, fmaf(wv.z, pv.z, fmaf(wv.w, pv.w, acc[j]))));
            }
        }
        float s = 0.f, sq = 0.f;
        #pragma unroll
        for (int j = 0; j < 4; ++j) {
            float v = acc[j];
            if (dorelu) v = fmaxf(v, 0.f);
            g_x[(size_t)(rowbase + slot + 4 * j) * 64 + c] = v;
            s += v; sq += v * v;
        }
        red[t] = s; red2[t] = sq;
        __syncthreads();
        if (slot == 0) {
            atomicAdd(&g_stats[c],      red[c] + red[64 + c] + red[128 + c] + red[192 + c]);
            atomicAdd(&g_stats[64 + c], red2[c] + red2[64 + c] + red2[128 + c] + red2[192 + c]);
        }
    }

    // ---- phase 2 (all blocks): dynamic pop over lg [0,EE) then pm [EE,EE+NN) ----
    while (true) {
        unsigned rowid;
        if (lane == 0) rowid = atomicAdd(&g_row_ctr, 1u);
        rowid = __shfl_sync(0xffffffffu, rowid, 0);
        if (rowid >= POPROWS) return;

        if (rowid < EE) {
            int row = (int)rowid;
            const float4* arow = reinterpret_cast<const float4*>(lg + (size_t)row * EE);
            float acc0, acc1;
            scan_gather_row(arow, y, lane, acc0, acc1);
            g_lg_y[(size_t)row * FDIM + lane]      = acc0;
            g_lg_y[(size_t)row * FDIM + lane + 32] = acc1;
        } else {
            int row = (int)rowid - EE;
            const float4* arow = reinterpret_cast<const float4*>(pm + (size_t)row * EE);
            #pragma unroll 1
            for (int g = 0; g < EE / 512; ++g) {
                int fb = (g << 7) + lane;
                float4 v0 = __ldcs(arow + fb);
                float4 v1 = __ldcs(arow + fb + 32);
                float4 v2 = __ldcs(arow + fb + 64);
                float4 v3 = __ldcs(arow + fb + 96);
                unsigned o0 = nz4(v0), o1 = nz4(v1), o2 = nz4(v2), o3 = nz4(v3);
                if (__ballot_sync(0xffffffffu, (o0 | o1 | o2 | o3) != 0u)) {
                    int cb = (g << 9) + (lane << 2);
                    if (o0) pm_emit(v0, cb,       row);
                    if (o1) pm_emit(v1, cb + 128, row);
                    if (o2) pm_emit(v2, cb + 256, row);
                    if (o3) pm_emit(v3, cb + 384, row);
                }
            }
        }
    }
}

// ---------------- y: inline pm gather (BN-x fused) + combine + relu + BN-y stats -> out ----------------
__global__ __launch_bounds__(256) void k_y_linear(const float* __restrict__ gaw,
                                                  const float* __restrict__ gab,
                                                  const float* __restrict__ gxw,
                                                  const float* __restrict__ gxb,
                                                  const float* __restrict__ garw,
                                                  const float* __restrict__ garb,
                                                  const float* __restrict__ gxrw,
                                                  const float* __restrict__ gxrb,
                                                  const float* __restrict__ bxw,
                                                  const float* __restrict__ bxb,
                                                  float* __restrict__ out) {
    __shared__ float s_lg[16 * 64];
    __shared__ float s_pm[16 * 64];
    __shared__ float s_sc[64], s_sh[64];
    __shared__ float red[256], red2[256];
    int t = threadIdx.x;
    int lane = t & 31;
    int w = t >> 5;
    int rowbase = blockIdx.x * 16;

    if (t < 64) {
        const float invn = 1.f / NN;
        float m = g_stats[t] * invn;
        float var = g_stats[64 + t] * invn - m * m;
        float sc = bxw[t] * rsqrtf(var + BN_EPS);
        s_sc[t] = sc;
        s_sh[t] = bxb[t] - m * sc;
    }
    reinterpret_cast<float4*>(s_lg)[t] =
        reinterpret_cast<const float4*>(g_lg_y + (size_t)rowbase * 64)[t];
    __syncthreads();

    // pm gather: warp w handles edges rowbase+2w, rowbase+2w+1
    {
        float scl0 = s_sc[lane],      shl0 = s_sh[lane];
        float scl1 = s_sc[lane + 32], shl1 = s_sh[lane + 32];
        #pragma unroll
        for (int h = 0; h < 2; ++h) {
            int eslot = 2 * w + h;
            int e = rowbase + eslot;
            int cnt = g_bkt_cnt[e];
            if (cnt > BKT) cnt = BKT;
            float a0 = 0.f, a1 = 0.f;
            for (int j = 0; j < cnt; ++j) {
                int n = g_bkt_n[e * BKT + j];
                float val = g_bkt_v[e * BKT + j];
                float xv0 = g_x[(size_t)n * 64 + lane];
                float xv1 = g_x[(size_t)n * 64 + lane + 32];
                a0 = fmaf(val, fmaf(xv0, scl0, shl0), a0);
                a1 = fmaf(val, fmaf(xv1, scl1, shl1), a1);
            }
            s_pm[eslot * 64 + lane]      = a0;
            s_pm[eslot * 64 + lane + 32] = a1;
        }
    }
    __syncthreads();

    int c = t & 63, slot = t >> 6;
    const float *wa, *wx; float bias; bool dorelu;
    if (c < 32) { wa = gaw + c * 64;   wx = gxw + c * 64;
                  bias = gab[c] + gxb[c];            dorelu = false; }
    else        { int cr = c - 32;
                  wa = garw + cr * 64; wx = gxrw + cr * 64;
                  bias = garb[cr] + gxrb[cr];        dorelu = true;  }
    float acc[4] = {bias, bias, bias, bias};
    #pragma unroll
    for (int f = 0; f < 64; f += 4) {
        float4 wav = *reinterpret_cast<const float4*>(wa + f);
        float4 wxv = *reinterpret_cast<const float4*>(wx + f);
        #pragma unroll
        for (int j = 0; j < 4; ++j) {
            float4 pa = *reinterpret_cast<const float4*>(&s_lg[(slot + 4 * j) * 64 + f]);
            float4 px = *reinterpret_cast<const float4*>(&s_pm[(slot + 4 * j) * 64 + f]);
            float a = acc[j];
            a = fmaf(wav.x, pa.x, fmaf(wav.y, pa.y, fmaf(wav.z, pa.z, fmaf(wav.w, pa.w, a))));
            a = fmaf(wxv.x, px.x, fmaf(wxv.y, px.y, fmaf(wxv.z, px.z, fmaf(wxv.w, px.w, a))));
            acc[j] = a;
        }
    }
    float s = 0.f, sq = 0.f;
    #pragma unroll
    for (int j = 0; j < 4; ++j) {
        float v = acc[j];
        if (dorelu) v = fmaxf(v, 0.f);
        out[(size_t)(rowbase + slot + 4 * j) * 64 + c] = v;
        s += v; sq += v * v;
    }
    red[t] = s; red2[t] = sq;
    __syncthreads();
    if (slot == 0) {
        atomicAdd(&g_stats[128 + c], red[c] + red[64 + c] + red[128 + c] + red[192 + c]);
        atomicAdd(&g_stats[192 + c], red2[c] + red2[64 + c] + red2[128 + c] + red2[192 + c]);
    }
}

// ---------------- final BN on y (vectorized, in place) + state recycle for next replay ----------------
__global__ __launch_bounds__(256) void k_bn_y(float4* __restrict__ buf,
                                              const float* __restrict__ w,
                                              const float* __restrict__ b) {
    int idx = blockIdx.x * 256 + threadIdx.x;   // 512*256 = 131072

    // recycle state consumed earlier this replay (next consumer: next replay's megascan)
    if (idx < EE) g_bkt_cnt[idx] = 0;
    if (idx < 128) g_stats[idx] = 0.f;
    if (idx == 0) g_row_ctr = 0u;

    const float inve = 1.f / EE;
    int c0 = (idx & 15) << 2;
    float4 v = buf[idx];
    float* vp = reinterpret_cast<float*>(&v);
    #pragma unroll
    for (int j = 0; j < 4; ++j) {
        int c = c0 + j;
        float m = g_stats[128 + c] * inve;
        float var = g_stats[192 + c] * inve - m * m;
        float sc = w[c] * rsqrtf(var + BN_EPS);
        vp[j] = (vp[j] - m) * sc + b[c];
    }
    buf[idx] = v;
}

// ---------------- launch (3 kernels) ----------------
extern "C" void kernel_launch(void* const* d_in, const int* in_sizes, int n_in,
                              void* d_out, int out_size) {
    const float* y    = (const float*)d_in[0];
    const float* lg   = (const float*)d_in[3];
    const float* pm   = (const float*)d_in[4];
    const float* pd   = (const float*)d_in[5];
    const float* tw   = (const float*)d_in[6];
    const float* tb   = (const float*)d_in[7];
    const float* trw  = (const float*)d_in[8];
    const float* trb  = (const float*)d_in[9];
    const float* gaw  = (const float*)d_in[10];
    const float* gab  = (const float*)d_in[11];
    const float* gxw  = (const float*)d_in[12];
    const float* gxb  = (const float*)d_in[13];
    const float* garw = (const float*)d_in[14];
    const float* garb = (const float*)d_in[15];
    const float* gxrw = (const float*)d_in[16];
    const float* gxrb = (const float*)d_in[17];
    const float* bxw  = (const float*)d_in[18];
    const float* bxb  = (const float*)d_in[19];
    const float* byw  = (const float*)d_in[20];
    const float* byb  = (const float*)d_in[21];
    float* out = (float*)d_out;

    k_megascan<<<NBLK, 256>>>(pd, lg, pm, y, tw, tb, trw, trb);
    k_y_linear<<<EE / 16, 256>>>(gaw, gab, gxw, gxb, garw, garb, gxrw, gxrb,
                                 bxw, bxb, out);
    k_bn_y<<<512, 256>>>((float4*)out, byw, byb);
}